// round 5
// baseline (speedup 1.0000x reference)
#include <cuda_runtime.h>
#include <cuda_bf16.h>
#include <stdint.h>

// Problem constants (feature dims fixed by dataset; counts from in_sizes)
#define NIN  128
#define NOUT 128
#define MAX_N 100000
#define MAX_E 1600000
#define SCAN_B 1024
#define MAX_SCAN_BLOCKS 128   // ceil(MAX_N / SCAN_B) = 98

// ------------- scratch: __device__ globals, referenced ONLY from device code --
__device__ __align__(16) int   g_cnt[MAX_N];      // per-dst edge count (no self loop)
__device__ __align__(16) int   g_indptr[MAX_N];   // CSR row start
__device__ __align__(16) int   g_cursor[MAX_N];   // fill cursor
__device__ __align__(16) int   g_blksum[MAX_SCAN_BLOCKS];
__device__ __align__(16) float g_dinv[MAX_N];
__device__ __align__(16) int   g_eidx[MAX_E];     // CSR payload: src node per edge
__device__ __align__(16) float g_g[(size_t)MAX_N * NOUT]; // g = (x@W^T)*dinv[row]

// ---------------- CSR build ---------------------------------------------------
// NOTE: edge_index is int32 (JAX default x64-disabled downcasts jnp.int64).

__global__ void cnt_init_kernel(int n) {
    int i = blockIdx.x * blockDim.x + threadIdx.x;
    if (i < n) g_cnt[i] = 0;
}

__global__ void cnt_count_kernel(const int* __restrict__ ei, int E, int n) {
    int e = blockIdx.x * blockDim.x + threadIdx.x;
    if (e < E) {
        int dst = ei[E + e];
        if ((unsigned)dst < (unsigned)n)   // guard: never trap on unexpected data
            atomicAdd(&g_cnt[dst], 1);
    }
}

// Per-block exclusive scan of g_cnt into g_indptr; writes block totals to g_blksum.
__global__ __launch_bounds__(SCAN_B) void scan_block_kernel(int n) {
    __shared__ int warpsum[32];
    int tid = threadIdx.x;
    int i = blockIdx.x * SCAN_B + tid;
    int v = (i < n) ? g_cnt[i] : 0;
    int x = v;
    #pragma unroll
    for (int o = 1; o < 32; o <<= 1) {
        int t = __shfl_up_sync(0xFFFFFFFFu, x, o);
        if ((tid & 31) >= o) x += t;
    }
    if ((tid & 31) == 31) warpsum[tid >> 5] = x;
    __syncthreads();
    if (tid < 32) {
        int s = warpsum[tid];
        #pragma unroll
        for (int o = 1; o < 32; o <<= 1) {
            int t = __shfl_up_sync(0xFFFFFFFFu, s, o);
            if (tid >= o) s += t;
        }
        warpsum[tid] = s;
    }
    __syncthreads();
    int wid = tid >> 5;
    int base = (wid > 0) ? warpsum[wid - 1] : 0;
    int incl = base + x;
    if (i < n) g_indptr[i] = incl - v;   // exclusive within block
    if (tid == SCAN_B - 1) g_blksum[blockIdx.x] = incl;
}

// Tiny sequential exclusive scan of block sums (nb <= 128).
__global__ void scan_tops_kernel(int nb) {
    if (threadIdx.x == 0 && blockIdx.x == 0) {
        int run = 0;
        for (int j = 0; j < nb; j++) { int t = g_blksum[j]; g_blksum[j] = run; run += t; }
    }
}

// Add block offsets; init cursor; compute dinv = rsqrt(deg+1) (self loop).
__global__ void addback_kernel(int n) {
    int i = blockIdx.x * blockDim.x + threadIdx.x;
    if (i < n) {
        int p = g_indptr[i] + g_blksum[i >> 10];
        g_indptr[i] = p;
        g_cursor[i] = p;
        g_dinv[i] = rsqrtf((float)(g_cnt[i] + 1));
    }
}

__global__ void fill_kernel(const int* __restrict__ ei, int E, int n) {
    int e = blockIdx.x * blockDim.x + threadIdx.x;
    if (e < E) {
        int src = ei[e];
        int dst = ei[E + e];
        if ((unsigned)dst < (unsigned)n && (unsigned)src < (unsigned)n) {
            int pos = atomicAdd(&g_cursor[dst], 1);
            if ((unsigned)pos < (unsigned)MAX_E) g_eidx[pos] = src;
        }
    }
}

// ---------------- GEMM: g_g[m][o] = dinv[m] * sum_k x[m][k]*W[o][k] -----------
#define BM 64
#define BK 16
__global__ __launch_bounds__(256) void gemm_kernel(
    const float* __restrict__ x, const float* __restrict__ W, int n)
{
    __shared__ float Xs[BK][BM + 4];
    __shared__ float Ws[BK][NOUT + 4];

    const int tid = threadIdx.x;
    const int tx  = tid & 31;   // cols tx*4..tx*4+3
    const int ty  = tid >> 5;   // rows ty*8..ty*8+7 (uniform per warp)
    const int rowBase = blockIdx.x * BM;

    float acc[8][4];
    #pragma unroll
    for (int r = 0; r < 8; r++)
        #pragma unroll
        for (int c = 0; c < 4; c++) acc[r][c] = 0.0f;

    const int lm = tid >> 2;
    const int lk = (tid & 3) * 4;

    for (int kb = 0; kb < NIN; kb += BK) {
        int gm = rowBase + lm;
        float4 xv = make_float4(0.f, 0.f, 0.f, 0.f);
        if (gm < n) xv = *reinterpret_cast<const float4*>(&x[(size_t)gm * NIN + kb + lk]);
        Xs[lk + 0][lm] = xv.x;
        Xs[lk + 1][lm] = xv.y;
        Xs[lk + 2][lm] = xv.z;
        Xs[lk + 3][lm] = xv.w;

        #pragma unroll
        for (int i = 0; i < 8; i++) {
            int idx = tid + i * 256;
            int o  = idx >> 4;
            int kk = idx & 15;
            Ws[kk][o] = W[(size_t)o * NIN + kb + kk];
        }
        __syncthreads();

        #pragma unroll
        for (int kk = 0; kk < BK; kk++) {
            float4 wv = *reinterpret_cast<const float4*>(&Ws[kk][tx * 4]);
            float4 xa = *reinterpret_cast<const float4*>(&Xs[kk][ty * 8]);
            float4 xb = *reinterpret_cast<const float4*>(&Xs[kk][ty * 8 + 4]);
            float xr[8] = {xa.x, xa.y, xa.z, xa.w, xb.x, xb.y, xb.z, xb.w};
            float wc[4] = {wv.x, wv.y, wv.z, wv.w};
            #pragma unroll
            for (int r = 0; r < 8; r++)
                #pragma unroll
                for (int c = 0; c < 4; c++)
                    acc[r][c] = fmaf(xr[r], wc[c], acc[r][c]);
        }
        __syncthreads();
    }

    #pragma unroll
    for (int r = 0; r < 8; r++) {
        int m = rowBase + ty * 8 + r;
        if (m < n) {
            float s = g_dinv[m];
            float4 v = make_float4(acc[r][0] * s, acc[r][1] * s, acc[r][2] * s, acc[r][3] * s);
            *reinterpret_cast<float4*>(&g_g[(size_t)m * NOUT + tx * 4]) = v;
        }
    }
}

// ---------------- Pull aggregation: one warp per destination node -------------
// out[i] = dinv[i] * (g[i] + sum_{e in CSR[i]} g[src_e]) + b   (no FP atomics)
__global__ __launch_bounds__(256) void aggregate_kernel(
    float* __restrict__ out, const float* __restrict__ b, int n)
{
    const float4* g4 = reinterpret_cast<const float4*>(g_g);
    int w    = (blockIdx.x * blockDim.x + threadIdx.x) >> 5;
    int lane = threadIdx.x & 31;
    if (w >= n) return;

    float4 acc = g4[(size_t)w * 32 + lane];   // self-loop term
    int beg = g_indptr[w];
    int num = g_cnt[w];

    int e = 0;
    // 4-way unrolled: 4 outstanding 16B gathers per lane to hide L2 latency
    for (; e + 3 < num; e += 4) {
        int s0 = g_eidx[beg + e];
        int s1 = g_eidx[beg + e + 1];
        int s2 = g_eidx[beg + e + 2];
        int s3 = g_eidx[beg + e + 3];
        float4 v0 = g4[(size_t)s0 * 32 + lane];
        float4 v1 = g4[(size_t)s1 * 32 + lane];
        float4 v2 = g4[(size_t)s2 * 32 + lane];
        float4 v3 = g4[(size_t)s3 * 32 + lane];
        acc.x += (v0.x + v1.x) + (v2.x + v3.x);
        acc.y += (v0.y + v1.y) + (v2.y + v3.y);
        acc.z += (v0.z + v1.z) + (v2.z + v3.z);
        acc.w += (v0.w + v1.w) + (v2.w + v3.w);
    }
    for (; e < num; e++) {
        int s0 = g_eidx[beg + e];
        float4 v0 = g4[(size_t)s0 * 32 + lane];
        acc.x += v0.x; acc.y += v0.y; acc.z += v0.z; acc.w += v0.w;
    }

    float sdi = g_dinv[w];
    const float4* b4 = reinterpret_cast<const float4*>(b);
    float4 bb = b4[lane];
    float4 o;
    o.x = fmaf(acc.x, sdi, bb.x);
    o.y = fmaf(acc.y, sdi, bb.y);
    o.z = fmaf(acc.z, sdi, bb.z);
    o.w = fmaf(acc.w, sdi, bb.w);
    reinterpret_cast<float4*>(out)[(size_t)w * 32 + lane] = o;
}

// ---------------- launch ------------------------------------------------------

extern "C" void kernel_launch(void* const* d_in, const int* in_sizes, int n_in,
                              void* d_out, int out_size) {
    const float* x  = (const float*)d_in[0];
    const int*   ei = (const int*)d_in[1];     // int32! (JAX x64 disabled)
    // d_in[2] = edge_attr (unused by GCNConv)
    const float* W  = (const float*)d_in[3];
    const float* b  = (const float*)d_in[4];
    float*       out = (float*)d_out;

    int n = in_sizes[0] / NIN;
    int E = in_sizes[1] / 2;
    int nb = (n + SCAN_B - 1) / SCAN_B;

    cnt_init_kernel<<<(n + 255) / 256, 256>>>(n);
    cnt_count_kernel<<<(E + 255) / 256, 256>>>(ei, E, n);
    scan_block_kernel<<<nb, SCAN_B>>>(n);
    scan_tops_kernel<<<1, 32>>>(nb);
    addback_kernel<<<(n + 255) / 256, 256>>>(n);
    fill_kernel<<<(E + 255) / 256, 256>>>(ei, E, n);

    gemm_kernel<<<(n + BM - 1) / BM, 256>>>(x, W, n);

    long long agg_threads = (long long)n * 32;
    aggregate_kernel<<<(int)((agg_threads + 255) / 256), 256>>>(out, b, n);
}

// round 7
// speedup vs baseline: 1.0927x; 1.0927x over previous
#include <cuda_runtime.h>
#include <cuda_bf16.h>
#include <stdint.h>

#define NIN  128
#define NOUT 128
#define MAX_N 100000
#define MAX_E 1600000
#define SCAN_B 1024
#define MAX_SCAN_BLOCKS 128

// ------------- scratch: __device__ globals, device-code access only -----------
__device__ __align__(16) int   g_cnt[MAX_N];
__device__ __align__(16) int   g_indptr[MAX_N];
__device__ __align__(16) int   g_cursor[MAX_N];
__device__ __align__(16) int   g_blksum[MAX_SCAN_BLOCKS];
__device__ __align__(16) float g_dinv[MAX_N];
__device__ __align__(16) int   g_eidx[MAX_E];
__device__ __align__(16) float g_g[(size_t)MAX_N * NOUT];

// ---------------- CSR build (edge_index is int32) -----------------------------

__global__ void cnt_init_kernel(int n) {
    int i = blockIdx.x * blockDim.x + threadIdx.x;
    if (i < n) g_cnt[i] = 0;
}

__global__ void cnt_count_kernel(const int* __restrict__ ei, int E, int n) {
    int e = blockIdx.x * blockDim.x + threadIdx.x;
    if (e < E) {
        int dst = ei[E + e];
        if ((unsigned)dst < (unsigned)n) atomicAdd(&g_cnt[dst], 1);
    }
}

__global__ __launch_bounds__(SCAN_B) void scan_block_kernel(int n) {
    __shared__ int warpsum[32];
    int tid = threadIdx.x;
    int i = blockIdx.x * SCAN_B + tid;
    int v = (i < n) ? g_cnt[i] : 0;
    int x = v;
    #pragma unroll
    for (int o = 1; o < 32; o <<= 1) {
        int t = __shfl_up_sync(0xFFFFFFFFu, x, o);
        if ((tid & 31) >= o) x += t;
    }
    if ((tid & 31) == 31) warpsum[tid >> 5] = x;
    __syncthreads();
    if (tid < 32) {
        int s = warpsum[tid];
        #pragma unroll
        for (int o = 1; o < 32; o <<= 1) {
            int t = __shfl_up_sync(0xFFFFFFFFu, s, o);
            if (tid >= o) s += t;
        }
        warpsum[tid] = s;
    }
    __syncthreads();
    int wid = tid >> 5;
    int base = (wid > 0) ? warpsum[wid - 1] : 0;
    int incl = base + x;
    if (i < n) g_indptr[i] = incl - v;
    if (tid == SCAN_B - 1) g_blksum[blockIdx.x] = incl;
}

// Parallel exclusive scan over block sums (nb <= 128), one 128-thread block.
__global__ void scan_tops_kernel(int nb) {
    __shared__ int ws[4];
    int tid = threadIdx.x;
    int v = (tid < nb) ? g_blksum[tid] : 0;
    int x = v;
    #pragma unroll
    for (int o = 1; o < 32; o <<= 1) {
        int t = __shfl_up_sync(0xFFFFFFFFu, x, o);
        if ((tid & 31) >= o) x += t;
    }
    if ((tid & 31) == 31) ws[tid >> 5] = x;
    __syncthreads();
    int base = 0;
    #pragma unroll
    for (int w = 0; w < 4; w++) if ((tid >> 5) > w) base += ws[w];
    if (tid < nb) g_blksum[tid] = base + x - v;   // exclusive
}

__global__ void addback_kernel(int n) {
    int i = blockIdx.x * blockDim.x + threadIdx.x;
    if (i < n) {
        int p = g_indptr[i] + g_blksum[i >> 10];
        g_indptr[i] = p;
        g_cursor[i] = p;
        g_dinv[i] = rsqrtf((float)(g_cnt[i] + 1));
    }
}

__global__ void fill_kernel(const int* __restrict__ ei, int E, int n) {
    int e = blockIdx.x * blockDim.x + threadIdx.x;
    if (e < E) {
        int src = ei[e];
        int dst = ei[E + e];
        if ((unsigned)dst < (unsigned)n && (unsigned)src < (unsigned)n) {
            int pos = atomicAdd(&g_cursor[dst], 1);
            if ((unsigned)pos < (unsigned)MAX_E) g_eidx[pos] = src;
        }
    }
}

// ---------------- mma.sync tf32 GEMM: g = dinv[m] * (x @ W^T) -----------------
// 3xTF32 error compensation: acc += Ahi*Bhi + Ahi*Blo + Alo*Bhi.
// Block tile 128x128, K in 4 chunks of 32. 8 warps (4 M-groups x 2 N-groups);
// warp tile 32 rows x 64 cols = 2 m16 tiles x 8 n8 tiles, mma.m16n8k8.

__device__ __forceinline__ float to_tf32(float f) {
    float r; asm("cvt.rna.tf32.f32 %0, %1;" : "=f"(r) : "f"(f)); return r;
}
__device__ __forceinline__ void mma8(float* c, const uint32_t* a, uint32_t b0, uint32_t b1) {
    asm volatile(
        "mma.sync.aligned.m16n8k8.row.col.f32.tf32.tf32.f32 "
        "{%0,%1,%2,%3}, {%4,%5,%6,%7}, {%8,%9}, {%0,%1,%2,%3};"
        : "+f"(c[0]), "+f"(c[1]), "+f"(c[2]), "+f"(c[3])
        : "r"(a[0]), "r"(a[1]), "r"(a[2]), "r"(a[3]), "r"(b0), "r"(b1));
}

#define KC 32          // K chunk
#define ASTRIDE 36     // 32 + 4 pad: banks = (36*row + col) % 32 = (4*row+col)%32

__global__ __launch_bounds__(256, 2) void gemm_mma_kernel(
    const float* __restrict__ x, const float* __restrict__ W, int n)
{
    __shared__ float As[128][ASTRIDE];
    __shared__ float Bs[128][ASTRIDE];

    const int tid  = threadIdx.x;
    const int wid  = tid >> 5;
    const int lane = tid & 31;
    const int gq   = lane >> 2;   // groupID 0..7
    const int tq   = lane & 3;    // threadID_in_group 0..3
    const int warpM = wid & 3;    // rows warpM*32
    const int warpN = wid >> 2;   // cols warpN*64
    const int rowBase = blockIdx.x * 128;

    float acc[2][8][4];
    #pragma unroll
    for (int mt = 0; mt < 2; mt++)
        #pragma unroll
        for (int nt = 0; nt < 8; nt++)
            #pragma unroll
            for (int q = 0; q < 4; q++) acc[mt][nt][q] = 0.0f;

    #pragma unroll
    for (int chunk = 0; chunk < 4; chunk++) {
        // ---- stage fp32 tiles: x rows (guarded) and W rows ----
        #pragma unroll
        for (int it = 0; it < 4; it++) {
            int gid = tid + it * 256;       // 0..1023
            int row = gid >> 3;             // 0..127
            int f4  = gid & 7;              // 0..7
            int gm = rowBase + row;
            float4 av = make_float4(0.f, 0.f, 0.f, 0.f);
            if (gm < n) av = *reinterpret_cast<const float4*>(&x[(size_t)gm * NIN + chunk * KC + f4 * 4]);
            *reinterpret_cast<float4*>(&As[row][f4 * 4]) = av;
            float4 bv = *reinterpret_cast<const float4*>(&W[(size_t)row * NIN + chunk * KC + f4 * 4]);
            *reinterpret_cast<float4*>(&Bs[row][f4 * 4]) = bv;
        }
        __syncthreads();

        #pragma unroll
        for (int ks = 0; ks < 4; ks++) {
            // A fragments (hi/lo) for 2 m16 tiles
            uint32_t ahi[2][4], alo[2][4];
            #pragma unroll
            for (int mt = 0; mt < 2; mt++) {
                int r0 = warpM * 32 + mt * 16 + gq;
                int c0 = ks * 8 + tq;
                float v0 = As[r0][c0];
                float v1 = As[r0 + 8][c0];
                float v2 = As[r0][c0 + 4];
                float v3 = As[r0 + 8][c0 + 4];
                float h0 = to_tf32(v0), h1 = to_tf32(v1), h2 = to_tf32(v2), h3 = to_tf32(v3);
                ahi[mt][0] = __float_as_uint(h0);
                ahi[mt][1] = __float_as_uint(h1);
                ahi[mt][2] = __float_as_uint(h2);
                ahi[mt][3] = __float_as_uint(h3);
                alo[mt][0] = __float_as_uint(to_tf32(v0 - h0));
                alo[mt][1] = __float_as_uint(to_tf32(v1 - h1));
                alo[mt][2] = __float_as_uint(to_tf32(v2 - h2));
                alo[mt][3] = __float_as_uint(to_tf32(v3 - h3));
            }
            #pragma unroll
            for (int nt = 0; nt < 8; nt++) {
                int nrow = warpN * 64 + nt * 8 + gq;
                float w0 = Bs[nrow][ks * 8 + tq];
                float w1 = Bs[nrow][ks * 8 + tq + 4];
                float h0 = to_tf32(w0), h1 = to_tf32(w1);
                uint32_t bh0 = __float_as_uint(h0), bh1 = __float_as_uint(h1);
                uint32_t bl0 = __float_as_uint(to_tf32(w0 - h0));
                uint32_t bl1 = __float_as_uint(to_tf32(w1 - h1));
                #pragma unroll
                for (int mt = 0; mt < 2; mt++) {
                    mma8(acc[mt][nt], ahi[mt], bh0, bh1);
                    mma8(acc[mt][nt], ahi[mt], bl0, bl1);
                    mma8(acc[mt][nt], alo[mt], bh0, bh1);
                }
            }
        }
        __syncthreads();
    }

    // ---- epilogue: scale by dinv[row], write g_g ----
    #pragma unroll
    for (int mt = 0; mt < 2; mt++) {
        int r0 = rowBase + warpM * 32 + mt * 16 + gq;
        int r1 = r0 + 8;
        float s0 = (r0 < n) ? g_dinv[r0] : 0.0f;
        float s1 = (r1 < n) ? g_dinv[r1] : 0.0f;
        #pragma unroll
        for (int nt = 0; nt < 8; nt++) {
            int c = warpN * 64 + nt * 8 + 2 * tq;
            if (r0 < n) {
                float2 v = make_float2(acc[mt][nt][0] * s0, acc[mt][nt][1] * s0);
                *reinterpret_cast<float2*>(&g_g[(size_t)r0 * NOUT + c]) = v;
            }
            if (r1 < n) {
                float2 v = make_float2(acc[mt][nt][2] * s1, acc[mt][nt][3] * s1);
                *reinterpret_cast<float2*>(&g_g[(size_t)r1 * NOUT + c]) = v;
            }
        }
    }
}

// ---------------- Pull aggregation: one warp per destination node -------------
__global__ __launch_bounds__(256) void aggregate_kernel(
    float* __restrict__ out, const float* __restrict__ b, int n)
{
    const float4* g4 = reinterpret_cast<const float4*>(g_g);
    int w    = (blockIdx.x * blockDim.x + threadIdx.x) >> 5;
    int lane = threadIdx.x & 31;
    if (w >= n) return;

    float4 acc = g4[(size_t)w * 32 + lane];   // self-loop term
    int beg = g_indptr[w];
    int num = g_cnt[w];

    int e = 0;
    for (; e + 3 < num; e += 4) {
        int s0 = g_eidx[beg + e];
        int s1 = g_eidx[beg + e + 1];
        int s2 = g_eidx[beg + e + 2];
        int s3 = g_eidx[beg + e + 3];
        float4 v0 = g4[(size_t)s0 * 32 + lane];
        float4 v1 = g4[(size_t)s1 * 32 + lane];
        float4 v2 = g4[(size_t)s2 * 32 + lane];
        float4 v3 = g4[(size_t)s3 * 32 + lane];
        acc.x += (v0.x + v1.x) + (v2.x + v3.x);
        acc.y += (v0.y + v1.y) + (v2.y + v3.y);
        acc.z += (v0.z + v1.z) + (v2.z + v3.z);
        acc.w += (v0.w + v1.w) + (v2.w + v3.w);
    }
    for (; e < num; e++) {
        int s0 = g_eidx[beg + e];
        float4 v0 = g4[(size_t)s0 * 32 + lane];
        acc.x += v0.x; acc.y += v0.y; acc.z += v0.z; acc.w += v0.w;
    }

    float sdi = g_dinv[w];
    const float4* b4 = reinterpret_cast<const float4*>(b);
    float4 bb = b4[lane];
    float4 o;
    o.x = fmaf(acc.x, sdi, bb.x);
    o.y = fmaf(acc.y, sdi, bb.y);
    o.z = fmaf(acc.z, sdi, bb.z);
    o.w = fmaf(acc.w, sdi, bb.w);
    reinterpret_cast<float4*>(out)[(size_t)w * 32 + lane] = o;
}

// ---------------- launch ------------------------------------------------------

extern "C" void kernel_launch(void* const* d_in, const int* in_sizes, int n_in,
                              void* d_out, int out_size) {
    const float* x  = (const float*)d_in[0];
    const int*   ei = (const int*)d_in[1];     // int32 (JAX x64 disabled)
    const float* W  = (const float*)d_in[3];
    const float* b  = (const float*)d_in[4];
    float*       out = (float*)d_out;

    int n = in_sizes[0] / NIN;
    int E = in_sizes[1] / 2;
    int nb = (n + SCAN_B - 1) / SCAN_B;

    cnt_init_kernel<<<(n + 255) / 256, 256>>>(n);
    cnt_count_kernel<<<(E + 255) / 256, 256>>>(ei, E, n);
    scan_block_kernel<<<nb, SCAN_B>>>(n);
    scan_tops_kernel<<<1, 128>>>(nb);
    addback_kernel<<<(n + 255) / 256, 256>>>(n);
    fill_kernel<<<(E + 255) / 256, 256>>>(ei, E, n);

    gemm_mma_kernel<<<(n + 127) / 128, 256>>>(x, W, n);

    long long agg_threads = (long long)n * 32;
    aggregate_kernel<<<(int)((agg_threads + 255) / 256), 256>>>(out, b, n);
}

// round 8
// speedup vs baseline: 1.1650x; 1.0662x over previous
#include <cuda_runtime.h>
#include <cuda_fp16.h>
#include <stdint.h>

#define NIN  128
#define NOUT 128
#define MAX_N 100000
#define MAX_E 1600000
#define SCAN_B 1024
#define MAX_SCAN_BLOCKS 128

// ------------- scratch: __device__ globals, device-code access only -----------
__device__ __align__(16) int     g_cnt[MAX_N];
__device__ __align__(16) int     g_indptr[MAX_N];
__device__ __align__(16) int     g_cursor[MAX_N];
__device__ __align__(16) int     g_blksum[MAX_SCAN_BLOCKS];
__device__ __align__(16) float   g_dinv[MAX_N];
__device__ __align__(16) int     g_eidx[MAX_E];
__device__ __align__(16) __half2 g_h[(size_t)MAX_N * (NOUT / 2)];  // fp16 messages

// ---------------- CSR build (edge_index is int32) -----------------------------

__global__ void cnt_init_kernel(int n) {
    int i = blockIdx.x * blockDim.x + threadIdx.x;
    if (i < n) g_cnt[i] = 0;
}

__global__ void cnt_count_kernel(const int* __restrict__ ei, int E, int n) {
    int e = blockIdx.x * blockDim.x + threadIdx.x;
    if (e < E) {
        int dst = ei[E + e];
        if ((unsigned)dst < (unsigned)n) atomicAdd(&g_cnt[dst], 1);
    }
}

__global__ __launch_bounds__(SCAN_B) void scan_block_kernel(int n) {
    __shared__ int warpsum[32];
    int tid = threadIdx.x;
    int i = blockIdx.x * SCAN_B + tid;
    int v = (i < n) ? g_cnt[i] : 0;
    int x = v;
    #pragma unroll
    for (int o = 1; o < 32; o <<= 1) {
        int t = __shfl_up_sync(0xFFFFFFFFu, x, o);
        if ((tid & 31) >= o) x += t;
    }
    if ((tid & 31) == 31) warpsum[tid >> 5] = x;
    __syncthreads();
    if (tid < 32) {
        int s = warpsum[tid];
        #pragma unroll
        for (int o = 1; o < 32; o <<= 1) {
            int t = __shfl_up_sync(0xFFFFFFFFu, s, o);
            if (tid >= o) s += t;
        }
        warpsum[tid] = s;
    }
    __syncthreads();
    int wid = tid >> 5;
    int base = (wid > 0) ? warpsum[wid - 1] : 0;
    int incl = base + x;
    if (i < n) g_indptr[i] = incl - v;
    if (tid == SCAN_B - 1) g_blksum[blockIdx.x] = incl;
}

__global__ void scan_tops_kernel(int nb) {
    __shared__ int ws[4];
    int tid = threadIdx.x;
    int v = (tid < nb) ? g_blksum[tid] : 0;
    int x = v;
    #pragma unroll
    for (int o = 1; o < 32; o <<= 1) {
        int t = __shfl_up_sync(0xFFFFFFFFu, x, o);
        if ((tid & 31) >= o) x += t;
    }
    if ((tid & 31) == 31) ws[tid >> 5] = x;
    __syncthreads();
    int base = 0;
    #pragma unroll
    for (int w = 0; w < 4; w++) if ((tid >> 5) > w) base += ws[w];
    if (tid < nb) g_blksum[tid] = base + x - v;   // exclusive
}

__global__ void addback_kernel(int n) {
    int i = blockIdx.x * blockDim.x + threadIdx.x;
    if (i < n) {
        int p = g_indptr[i] + g_blksum[i >> 10];
        g_indptr[i] = p;
        g_cursor[i] = p;
        g_dinv[i] = rsqrtf((float)(g_cnt[i] + 1));
    }
}

__global__ void fill_kernel(const int* __restrict__ ei, int E, int n) {
    int e = blockIdx.x * blockDim.x + threadIdx.x;
    if (e < E) {
        int src = ei[e];
        int dst = ei[E + e];
        if ((unsigned)dst < (unsigned)n && (unsigned)src < (unsigned)n) {
            int pos = atomicAdd(&g_cursor[dst], 1);
            if ((unsigned)pos < (unsigned)MAX_E) g_eidx[pos] = src;
        }
    }
}

// ---------------- mma.sync tf32 GEMM: g_h = half( dinv[m] * (x @ W^T) ) -------
// 3xTF32 error compensation: acc += Ahi*Bhi + Ahi*Blo + Alo*Bhi.

__device__ __forceinline__ float to_tf32(float f) {
    float r; asm("cvt.rna.tf32.f32 %0, %1;" : "=f"(r) : "f"(f)); return r;
}
__device__ __forceinline__ void mma8(float* c, const uint32_t* a, uint32_t b0, uint32_t b1) {
    asm volatile(
        "mma.sync.aligned.m16n8k8.row.col.f32.tf32.tf32.f32 "
        "{%0,%1,%2,%3}, {%4,%5,%6,%7}, {%8,%9}, {%0,%1,%2,%3};"
        : "+f"(c[0]), "+f"(c[1]), "+f"(c[2]), "+f"(c[3])
        : "r"(a[0]), "r"(a[1]), "r"(a[2]), "r"(a[3]), "r"(b0), "r"(b1));
}

#define KC 32
#define ASTRIDE 36

__global__ __launch_bounds__(256, 2) void gemm_mma_kernel(
    const float* __restrict__ x, const float* __restrict__ W, int n)
{
    __shared__ float As[128][ASTRIDE];
    __shared__ float Bs[128][ASTRIDE];

    const int tid  = threadIdx.x;
    const int wid  = tid >> 5;
    const int lane = tid & 31;
    const int gq   = lane >> 2;
    const int tq   = lane & 3;
    const int warpM = wid & 3;
    const int warpN = wid >> 2;
    const int rowBase = blockIdx.x * 128;

    float acc[2][8][4];
    #pragma unroll
    for (int mt = 0; mt < 2; mt++)
        #pragma unroll
        for (int nt = 0; nt < 8; nt++)
            #pragma unroll
            for (int q = 0; q < 4; q++) acc[mt][nt][q] = 0.0f;

    #pragma unroll
    for (int chunk = 0; chunk < 4; chunk++) {
        #pragma unroll
        for (int it = 0; it < 4; it++) {
            int gid = tid + it * 256;
            int row = gid >> 3;
            int f4  = gid & 7;
            int gm = rowBase + row;
            float4 av = make_float4(0.f, 0.f, 0.f, 0.f);
            if (gm < n) av = *reinterpret_cast<const float4*>(&x[(size_t)gm * NIN + chunk * KC + f4 * 4]);
            *reinterpret_cast<float4*>(&As[row][f4 * 4]) = av;
            float4 bv = *reinterpret_cast<const float4*>(&W[(size_t)row * NIN + chunk * KC + f4 * 4]);
            *reinterpret_cast<float4*>(&Bs[row][f4 * 4]) = bv;
        }
        __syncthreads();

        #pragma unroll
        for (int ks = 0; ks < 4; ks++) {
            uint32_t ahi[2][4], alo[2][4];
            #pragma unroll
            for (int mt = 0; mt < 2; mt++) {
                int r0 = warpM * 32 + mt * 16 + gq;
                int c0 = ks * 8 + tq;
                float v0 = As[r0][c0];
                float v1 = As[r0 + 8][c0];
                float v2 = As[r0][c0 + 4];
                float v3 = As[r0 + 8][c0 + 4];
                float h0 = to_tf32(v0), h1 = to_tf32(v1), h2 = to_tf32(v2), h3 = to_tf32(v3);
                ahi[mt][0] = __float_as_uint(h0);
                ahi[mt][1] = __float_as_uint(h1);
                ahi[mt][2] = __float_as_uint(h2);
                ahi[mt][3] = __float_as_uint(h3);
                alo[mt][0] = __float_as_uint(to_tf32(v0 - h0));
                alo[mt][1] = __float_as_uint(to_tf32(v1 - h1));
                alo[mt][2] = __float_as_uint(to_tf32(v2 - h2));
                alo[mt][3] = __float_as_uint(to_tf32(v3 - h3));
            }
            #pragma unroll
            for (int nt = 0; nt < 8; nt++) {
                int nrow = warpN * 64 + nt * 8 + gq;
                float w0 = Bs[nrow][ks * 8 + tq];
                float w1 = Bs[nrow][ks * 8 + tq + 4];
                float h0 = to_tf32(w0), h1 = to_tf32(w1);
                uint32_t bh0 = __float_as_uint(h0), bh1 = __float_as_uint(h1);
                uint32_t bl0 = __float_as_uint(to_tf32(w0 - h0));
                uint32_t bl1 = __float_as_uint(to_tf32(w1 - h1));
                #pragma unroll
                for (int mt = 0; mt < 2; mt++) {
                    mma8(acc[mt][nt], ahi[mt], bh0, bh1);
                    mma8(acc[mt][nt], ahi[mt], bl0, bl1);
                    mma8(acc[mt][nt], alo[mt], bh0, bh1);
                }
            }
        }
        __syncthreads();
    }

    // ---- epilogue: scale by dinv[row], convert to half2, write g_h ----
    #pragma unroll
    for (int mt = 0; mt < 2; mt++) {
        int r0 = rowBase + warpM * 32 + mt * 16 + gq;
        int r1 = r0 + 8;
        float s0 = (r0 < n) ? g_dinv[r0] : 0.0f;
        float s1 = (r1 < n) ? g_dinv[r1] : 0.0f;
        #pragma unroll
        for (int nt = 0; nt < 8; nt++) {
            int c = warpN * 64 + nt * 8 + 2 * tq;
            if (r0 < n)
                g_h[(size_t)r0 * 64 + (c >> 1)] =
                    __floats2half2_rn(acc[mt][nt][0] * s0, acc[mt][nt][1] * s0);
            if (r1 < n)
                g_h[(size_t)r1 * 64 + (c >> 1)] =
                    __floats2half2_rn(acc[mt][nt][2] * s1, acc[mt][nt][3] * s1);
        }
    }
}

// ---------------- Pull aggregation: one warp per destination node -------------
// out[i] = dinv[i] * (gh[i] + sum_{e in CSR[i]} gh[src_e]) + b
// fp16 gathers (8B/lane), fp32 accumulation.

__device__ __forceinline__ void acc_row(float4& acc, const uint2* gh2, int row, int lane) {
    uint2 v = gh2[(size_t)row * 32 + lane];
    __half2 h0 = *reinterpret_cast<__half2*>(&v.x);
    __half2 h1 = *reinterpret_cast<__half2*>(&v.y);
    float2 f0 = __half22float2(h0);
    float2 f1 = __half22float2(h1);
    acc.x += f0.x; acc.y += f0.y; acc.z += f1.x; acc.w += f1.y;
}

__global__ __launch_bounds__(256) void aggregate_kernel(
    float* __restrict__ out, const float* __restrict__ b, int n)
{
    const uint2* gh2 = reinterpret_cast<const uint2*>(g_h);
    int w    = (blockIdx.x * blockDim.x + threadIdx.x) >> 5;
    int lane = threadIdx.x & 31;
    if (w >= n) return;

    float4 acc = make_float4(0.f, 0.f, 0.f, 0.f);
    acc_row(acc, gh2, w, lane);     // self-loop term
    int beg = g_indptr[w];
    int num = g_cnt[w];

    int e = 0;
    for (; e + 3 < num; e += 4) {
        int s0 = g_eidx[beg + e];
        int s1 = g_eidx[beg + e + 1];
        int s2 = g_eidx[beg + e + 2];
        int s3 = g_eidx[beg + e + 3];
        uint2 v0 = gh2[(size_t)s0 * 32 + lane];
        uint2 v1 = gh2[(size_t)s1 * 32 + lane];
        uint2 v2 = gh2[(size_t)s2 * 32 + lane];
        uint2 v3 = gh2[(size_t)s3 * 32 + lane];
        float2 a0 = __half22float2(*reinterpret_cast<__half2*>(&v0.x));
        float2 b0 = __half22float2(*reinterpret_cast<__half2*>(&v0.y));
        float2 a1 = __half22float2(*reinterpret_cast<__half2*>(&v1.x));
        float2 b1 = __half22float2(*reinterpret_cast<__half2*>(&v1.y));
        float2 a2 = __half22float2(*reinterpret_cast<__half2*>(&v2.x));
        float2 b2 = __half22float2(*reinterpret_cast<__half2*>(&v2.y));
        float2 a3 = __half22float2(*reinterpret_cast<__half2*>(&v3.x));
        float2 b3 = __half22float2(*reinterpret_cast<__half2*>(&v3.y));
        acc.x += (a0.x + a1.x) + (a2.x + a3.x);
        acc.y += (a0.y + a1.y) + (a2.y + a3.y);
        acc.z += (b0.x + b1.x) + (b2.x + b3.x);
        acc.w += (b0.y + b1.y) + (b2.y + b3.y);
    }
    for (; e < num; e++) {
        acc_row(acc, gh2, g_eidx[beg + e], lane);
    }

    float sdi = g_dinv[w];
    const float4* b4 = reinterpret_cast<const float4*>(b);
    float4 bb = b4[lane];
    float4 o;
    o.x = fmaf(acc.x, sdi, bb.x);
    o.y = fmaf(acc.y, sdi, bb.y);
    o.z = fmaf(acc.z, sdi, bb.z);
    o.w = fmaf(acc.w, sdi, bb.w);
    reinterpret_cast<float4*>(out)[(size_t)w * 32 + lane] = o;
}

// ---------------- launch ------------------------------------------------------

extern "C" void kernel_launch(void* const* d_in, const int* in_sizes, int n_in,
                              void* d_out, int out_size) {
    const float* x  = (const float*)d_in[0];
    const int*   ei = (const int*)d_in[1];     // int32 (JAX x64 disabled)
    const float* W  = (const float*)d_in[3];
    const float* b  = (const float*)d_in[4];
    float*       out = (float*)d_out;

    int n = in_sizes[0] / NIN;
    int E = in_sizes[1] / 2;
    int nb = (n + SCAN_B - 1) / SCAN_B;

    cnt_init_kernel<<<(n + 255) / 256, 256>>>(n);
    cnt_count_kernel<<<(E + 255) / 256, 256>>>(ei, E, n);
    scan_block_kernel<<<nb, SCAN_B>>>(n);
    scan_tops_kernel<<<1, 128>>>(nb);
    addback_kernel<<<(n + 255) / 256, 256>>>(n);
    fill_kernel<<<(E + 255) / 256, 256>>>(ei, E, n);

    gemm_mma_kernel<<<(n + 127) / 128, 256>>>(x, W, n);

    long long agg_threads = (long long)n * 32;
    aggregate_kernel<<<(int)((agg_threads + 255) / 256), 256>>>(out, b, n);
}

// round 9
// speedup vs baseline: 1.1785x; 1.0116x over previous
#include <cuda_runtime.h>
#include <cuda_fp16.h>
#include <stdint.h>

#define NIN  128
#define NOUT 128
#define MAX_N 100000
#define MAX_E 1600000
#define SCAN_B 1024
#define MAX_SCAN_BLOCKS 128

// ------------- scratch: __device__ globals ------------------------------------
__device__ __align__(16) int     g_cnt[MAX_N];
__device__ __align__(16) int     g_indptr[MAX_N];
__device__ __align__(16) int     g_cursor[MAX_N];
__device__ __align__(16) int     g_blksum[MAX_SCAN_BLOCKS];
__device__ __align__(16) float   g_dinv[MAX_N];
__device__ __align__(16) int     g_eidx[MAX_E];
__device__ __align__(16) __half2 g_h[(size_t)MAX_N * (NOUT / 2)];  // fp16 messages

// ---------------- CSR build (edge_index is int32) -----------------------------

__global__ void cnt_count_kernel(const int* __restrict__ ei, int E, int n) {
    int e = blockIdx.x * blockDim.x + threadIdx.x;
    if (e < E) {
        int dst = ei[E + e];
        if ((unsigned)dst < (unsigned)n) atomicAdd(&g_cnt[dst], 1);
    }
}

__global__ __launch_bounds__(SCAN_B) void scan_block_kernel(int n) {
    __shared__ int warpsum[32];
    int tid = threadIdx.x;
    int i = blockIdx.x * SCAN_B + tid;
    int v = (i < n) ? g_cnt[i] : 0;
    int x = v;
    #pragma unroll
    for (int o = 1; o < 32; o <<= 1) {
        int t = __shfl_up_sync(0xFFFFFFFFu, x, o);
        if ((tid & 31) >= o) x += t;
    }
    if ((tid & 31) == 31) warpsum[tid >> 5] = x;
    __syncthreads();
    if (tid < 32) {
        int s = warpsum[tid];
        #pragma unroll
        for (int o = 1; o < 32; o <<= 1) {
            int t = __shfl_up_sync(0xFFFFFFFFu, s, o);
            if (tid >= o) s += t;
        }
        warpsum[tid] = s;
    }
    __syncthreads();
    int wid = tid >> 5;
    int base = (wid > 0) ? warpsum[wid - 1] : 0;
    int incl = base + x;
    if (i < n) g_indptr[i] = incl - v;
    if (tid == SCAN_B - 1) g_blksum[blockIdx.x] = incl;
}

// Fused: per-block prefix over blksum (<=98 values, one warp) + addback +
// cursor init + dinv. 256 threads/block; chunk index constant within block.
__global__ __launch_bounds__(256) void addback_kernel(int n) {
    __shared__ int P;
    int c0 = blockIdx.x >> 2;          // 1024-chunk index for this block
    if (threadIdx.x < 32) {
        int s = 0;
        for (int j = threadIdx.x; j < c0; j += 32) s += g_blksum[j];
        #pragma unroll
        for (int o = 16; o; o >>= 1) s += __shfl_down_sync(0xFFFFFFFFu, s, o);
        if (threadIdx.x == 0) P = s;
    }
    __syncthreads();
    int i = blockIdx.x * 256 + threadIdx.x;
    if (i < n) {
        int p = g_indptr[i] + P;
        g_indptr[i] = p;
        g_cursor[i] = p;
        g_dinv[i] = rsqrtf((float)(g_cnt[i] + 1));
    }
}

__global__ void fill_kernel(const int* __restrict__ ei, int E, int n) {
    int e = blockIdx.x * blockDim.x + threadIdx.x;
    if (e < E) {
        int src = ei[e];
        int dst = ei[E + e];
        if ((unsigned)dst < (unsigned)n && (unsigned)src < (unsigned)n) {
            int pos = atomicAdd(&g_cursor[dst], 1);
            if ((unsigned)pos < (unsigned)MAX_E) g_eidx[pos] = src;
        }
    }
}

// ---------------- mma.sync tf32 GEMM: g_h = half( dinv[m] * (x @ W^T) ) -------
__device__ __forceinline__ float to_tf32(float f) {
    float r; asm("cvt.rna.tf32.f32 %0, %1;" : "=f"(r) : "f"(f)); return r;
}
__device__ __forceinline__ void mma8(float* c, const uint32_t* a, uint32_t b0, uint32_t b1) {
    asm volatile(
        "mma.sync.aligned.m16n8k8.row.col.f32.tf32.tf32.f32 "
        "{%0,%1,%2,%3}, {%4,%5,%6,%7}, {%8,%9}, {%0,%1,%2,%3};"
        : "+f"(c[0]), "+f"(c[1]), "+f"(c[2]), "+f"(c[3])
        : "r"(a[0]), "r"(a[1]), "r"(a[2]), "r"(a[3]), "r"(b0), "r"(b1));
}

#define KC 32
#define ASTRIDE 36

__global__ __launch_bounds__(256, 2) void gemm_mma_kernel(
    const float* __restrict__ x, const float* __restrict__ W, int n)
{
    __shared__ float As[128][ASTRIDE];
    __shared__ float Bs[128][ASTRIDE];

    const int tid  = threadIdx.x;
    const int wid  = tid >> 5;
    const int lane = tid & 31;
    const int gq   = lane >> 2;
    const int tq   = lane & 3;
    const int warpM = wid & 3;
    const int warpN = wid >> 2;
    const int rowBase = blockIdx.x * 128;

    float acc[2][8][4];
    #pragma unroll
    for (int mt = 0; mt < 2; mt++)
        #pragma unroll
        for (int nt = 0; nt < 8; nt++)
            #pragma unroll
            for (int q = 0; q < 4; q++) acc[mt][nt][q] = 0.0f;

    #pragma unroll
    for (int chunk = 0; chunk < 4; chunk++) {
        #pragma unroll
        for (int it = 0; it < 4; it++) {
            int gid = tid + it * 256;
            int row = gid >> 3;
            int f4  = gid & 7;
            int gm = rowBase + row;
            float4 av = make_float4(0.f, 0.f, 0.f, 0.f);
            if (gm < n) av = *reinterpret_cast<const float4*>(&x[(size_t)gm * NIN + chunk * KC + f4 * 4]);
            *reinterpret_cast<float4*>(&As[row][f4 * 4]) = av;
            float4 bv = *reinterpret_cast<const float4*>(&W[(size_t)row * NIN + chunk * KC + f4 * 4]);
            *reinterpret_cast<float4*>(&Bs[row][f4 * 4]) = bv;
        }
        __syncthreads();

        #pragma unroll
        for (int ks = 0; ks < 4; ks++) {
            uint32_t ahi[2][4], alo[2][4];
            #pragma unroll
            for (int mt = 0; mt < 2; mt++) {
                int r0 = warpM * 32 + mt * 16 + gq;
                int c0 = ks * 8 + tq;
                float v0 = As[r0][c0];
                float v1 = As[r0 + 8][c0];
                float v2 = As[r0][c0 + 4];
                float v3 = As[r0 + 8][c0 + 4];
                float h0 = to_tf32(v0), h1 = to_tf32(v1), h2 = to_tf32(v2), h3 = to_tf32(v3);
                ahi[mt][0] = __float_as_uint(h0);
                ahi[mt][1] = __float_as_uint(h1);
                ahi[mt][2] = __float_as_uint(h2);
                ahi[mt][3] = __float_as_uint(h3);
                alo[mt][0] = __float_as_uint(to_tf32(v0 - h0));
                alo[mt][1] = __float_as_uint(to_tf32(v1 - h1));
                alo[mt][2] = __float_as_uint(to_tf32(v2 - h2));
                alo[mt][3] = __float_as_uint(to_tf32(v3 - h3));
            }
            #pragma unroll
            for (int nt = 0; nt < 8; nt++) {
                int nrow = warpN * 64 + nt * 8 + gq;
                float w0 = Bs[nrow][ks * 8 + tq];
                float w1 = Bs[nrow][ks * 8 + tq + 4];
                float h0 = to_tf32(w0), h1 = to_tf32(w1);
                uint32_t bh0 = __float_as_uint(h0), bh1 = __float_as_uint(h1);
                uint32_t bl0 = __float_as_uint(to_tf32(w0 - h0));
                uint32_t bl1 = __float_as_uint(to_tf32(w1 - h1));
                #pragma unroll
                for (int mt = 0; mt < 2; mt++) {
                    mma8(acc[mt][nt], ahi[mt], bh0, bh1);
                    mma8(acc[mt][nt], ahi[mt], bl0, bl1);
                    mma8(acc[mt][nt], alo[mt], bh0, bh1);
                }
            }
        }
        __syncthreads();
    }

    #pragma unroll
    for (int mt = 0; mt < 2; mt++) {
        int r0 = rowBase + warpM * 32 + mt * 16 + gq;
        int r1 = r0 + 8;
        float s0 = (r0 < n) ? g_dinv[r0] : 0.0f;
        float s1 = (r1 < n) ? g_dinv[r1] : 0.0f;
        #pragma unroll
        for (int nt = 0; nt < 8; nt++) {
            int c = warpN * 64 + nt * 8 + 2 * tq;
            if (r0 < n)
                g_h[(size_t)r0 * 64 + (c >> 1)] =
                    __floats2half2_rn(acc[mt][nt][0] * s0, acc[mt][nt][1] * s0);
            if (r1 < n)
                g_h[(size_t)r1 * 64 + (c >> 1)] =
                    __floats2half2_rn(acc[mt][nt][2] * s1, acc[mt][nt][3] * s1);
        }
    }
}

// ---------------- Pull aggregation: one warp per destination node -------------
__device__ __forceinline__ void acc_row(float4& acc, const uint2* gh2, int row, int lane) {
    uint2 v = gh2[(size_t)row * 32 + lane];
    float2 f0 = __half22float2(*reinterpret_cast<__half2*>(&v.x));
    float2 f1 = __half22float2(*reinterpret_cast<__half2*>(&v.y));
    acc.x += f0.x; acc.y += f0.y; acc.z += f1.x; acc.w += f1.y;
}

__global__ __launch_bounds__(256) void aggregate_kernel(
    float* __restrict__ out, const float* __restrict__ b, int n)
{
    const uint2* gh2 = reinterpret_cast<const uint2*>(g_h);
    int w    = (blockIdx.x * blockDim.x + threadIdx.x) >> 5;
    int lane = threadIdx.x & 31;
    if (w >= n) return;

    float4 acc = make_float4(0.f, 0.f, 0.f, 0.f);
    acc_row(acc, gh2, w, lane);     // self-loop term
    int beg = g_indptr[w];
    int num = g_cnt[w];

    int e = 0;
    // 8-way: 8 outstanding 8B gathers per lane
    for (; e + 7 < num; e += 8) {
        int   s[8];
        uint2 v[8];
        #pragma unroll
        for (int q = 0; q < 8; q++) s[q] = g_eidx[beg + e + q];
        #pragma unroll
        for (int q = 0; q < 8; q++) v[q] = gh2[(size_t)s[q] * 32 + lane];
        #pragma unroll
        for (int q = 0; q < 8; q++) {
            float2 f0 = __half22float2(*reinterpret_cast<__half2*>(&v[q].x));
            float2 f1 = __half22float2(*reinterpret_cast<__half2*>(&v[q].y));
            acc.x += f0.x; acc.y += f0.y; acc.z += f1.x; acc.w += f1.y;
        }
    }
    for (; e + 3 < num; e += 4) {
        int   s[4];
        uint2 v[4];
        #pragma unroll
        for (int q = 0; q < 4; q++) s[q] = g_eidx[beg + e + q];
        #pragma unroll
        for (int q = 0; q < 4; q++) v[q] = gh2[(size_t)s[q] * 32 + lane];
        #pragma unroll
        for (int q = 0; q < 4; q++) {
            float2 f0 = __half22float2(*reinterpret_cast<__half2*>(&v[q].x));
            float2 f1 = __half22float2(*reinterpret_cast<__half2*>(&v[q].y));
            acc.x += f0.x; acc.y += f0.y; acc.z += f1.x; acc.w += f1.y;
        }
    }
    for (; e < num; e++) acc_row(acc, gh2, g_eidx[beg + e], lane);

    float sdi = g_dinv[w];
    const float4* b4 = reinterpret_cast<const float4*>(b);
    float4 bb = b4[lane];
    float4 o;
    o.x = fmaf(acc.x, sdi, bb.x);
    o.y = fmaf(acc.y, sdi, bb.y);
    o.z = fmaf(acc.z, sdi, bb.z);
    o.w = fmaf(acc.w, sdi, bb.w);
    reinterpret_cast<float4*>(out)[(size_t)w * 32 + lane] = o;
}

// ---------------- launch ------------------------------------------------------

extern "C" void kernel_launch(void* const* d_in, const int* in_sizes, int n_in,
                              void* d_out, int out_size) {
    const float* x  = (const float*)d_in[0];
    const int*   ei = (const int*)d_in[1];     // int32 (JAX x64 disabled)
    const float* W  = (const float*)d_in[3];
    const float* b  = (const float*)d_in[4];
    float*       out = (float*)d_out;

    int n = in_sizes[0] / NIN;
    int E = in_sizes[1] / 2;
    int nb = (n + SCAN_B - 1) / SCAN_B;

    void* cnt_ptr = nullptr;
    cudaGetSymbolAddress(&cnt_ptr, g_cnt);
    cudaMemsetAsync(cnt_ptr, 0, (size_t)n * sizeof(int));

    cnt_count_kernel<<<(E + 255) / 256, 256>>>(ei, E, n);
    scan_block_kernel<<<nb, SCAN_B>>>(n);
    addback_kernel<<<(n + 255) / 256, 256>>>(n);
    fill_kernel<<<(E + 255) / 256, 256>>>(ei, E, n);

    gemm_mma_kernel<<<(n + 127) / 128, 256>>>(x, W, n);

    long long agg_threads = (long long)n * 32;
    aggregate_kernel<<<(int)((agg_threads + 255) / 256), 256>>>(out, b, n);
}

// round 10
// speedup vs baseline: 1.2465x; 1.0577x over previous
#include <cuda_runtime.h>
#include <cuda_fp16.h>
#include <stdint.h>

#define NIN  128
#define NOUT 128
#define MAX_N 100000
#define MAX_E 1600000
#define SCAN_B 1024
#define MAX_SCAN_BLOCKS 128

// ------------- scratch: __device__ globals ------------------------------------
__device__ __align__(16) int     g_cnt[MAX_N];
__device__ __align__(16) int     g_indptr[MAX_N];
__device__ __align__(16) int     g_cursor[MAX_N];
__device__ __align__(16) int     g_blksum[MAX_SCAN_BLOCKS];
__device__ __align__(16) float   g_dinv[MAX_N];
__device__ __align__(16) int     g_eidx[MAX_E];
__device__ __align__(16) __half2 g_h[(size_t)MAX_N * (NOUT / 2)];  // UNSCALED fp16 h = x@W^T

// ---------------- CSR build (edge_index is int32) -----------------------------

__global__ void cnt_count_kernel(const int* __restrict__ ei, int E, int n) {
    int e0 = (blockIdx.x * blockDim.x + threadIdx.x) * 4;
    #pragma unroll
    for (int q = 0; q < 4; q++) {
        int e = e0 + q;
        if (e < E) {
            int dst = ei[E + e];
            if ((unsigned)dst < (unsigned)n) atomicAdd(&g_cnt[dst], 1);
        }
    }
}

__global__ __launch_bounds__(SCAN_B) void scan_block_kernel(int n) {
    __shared__ int warpsum[32];
    int tid = threadIdx.x;
    int i = blockIdx.x * SCAN_B + tid;
    int v = (i < n) ? g_cnt[i] : 0;
    int x = v;
    #pragma unroll
    for (int o = 1; o < 32; o <<= 1) {
        int t = __shfl_up_sync(0xFFFFFFFFu, x, o);
        if ((tid & 31) >= o) x += t;
    }
    if ((tid & 31) == 31) warpsum[tid >> 5] = x;
    __syncthreads();
    if (tid < 32) {
        int s = warpsum[tid];
        #pragma unroll
        for (int o = 1; o < 32; o <<= 1) {
            int t = __shfl_up_sync(0xFFFFFFFFu, s, o);
            if (tid >= o) s += t;
        }
        warpsum[tid] = s;
    }
    __syncthreads();
    int wid = tid >> 5;
    int base = (wid > 0) ? warpsum[wid - 1] : 0;
    int incl = base + x;
    if (i < n) g_indptr[i] = incl - v;
    if (tid == SCAN_B - 1) g_blksum[blockIdx.x] = incl;
}

// Fused: per-block prefix over blksum + addback + cursor init + dinv.
__global__ __launch_bounds__(256) void addback_kernel(int n) {
    __shared__ int P;
    int c0 = blockIdx.x >> 2;
    if (threadIdx.x < 32) {
        int s = 0;
        for (int j = threadIdx.x; j < c0; j += 32) s += g_blksum[j];
        #pragma unroll
        for (int o = 16; o; o >>= 1) s += __shfl_down_sync(0xFFFFFFFFu, s, o);
        if (threadIdx.x == 0) P = s;
    }
    __syncthreads();
    int i = blockIdx.x * 256 + threadIdx.x;
    if (i < n) {
        int p = g_indptr[i] + P;
        g_indptr[i] = p;
        g_cursor[i] = p;
        g_dinv[i] = rsqrtf((float)(g_cnt[i] + 1));
    }
}

__global__ void fill_kernel(const int* __restrict__ ei, int E, int n) {
    int e0 = (blockIdx.x * blockDim.x + threadIdx.x) * 4;
    int src[4], dst[4];
    #pragma unroll
    for (int q = 0; q < 4; q++) {
        int e = e0 + q;
        src[q] = (e < E) ? ei[e] : -1;
        dst[q] = (e < E) ? ei[E + e] : -1;
    }
    #pragma unroll
    for (int q = 0; q < 4; q++) {
        if ((unsigned)dst[q] < (unsigned)n && (unsigned)src[q] < (unsigned)n) {
            int pos = atomicAdd(&g_cursor[dst[q]], 1);
            if ((unsigned)pos < (unsigned)MAX_E) g_eidx[pos] = src[q];
        }
    }
}

// ---------------- mma.sync tf32 GEMM: g_h = half( x @ W^T )  (no dinv) --------
__device__ __forceinline__ float to_tf32(float f) {
    float r; asm("cvt.rna.tf32.f32 %0, %1;" : "=f"(r) : "f"(f)); return r;
}
__device__ __forceinline__ void mma8(float* c, const uint32_t* a, uint32_t b0, uint32_t b1) {
    asm volatile(
        "mma.sync.aligned.m16n8k8.row.col.f32.tf32.tf32.f32 "
        "{%0,%1,%2,%3}, {%4,%5,%6,%7}, {%8,%9}, {%0,%1,%2,%3};"
        : "+f"(c[0]), "+f"(c[1]), "+f"(c[2]), "+f"(c[3])
        : "r"(a[0]), "r"(a[1]), "r"(a[2]), "r"(a[3]), "r"(b0), "r"(b1));
}

#define KC 32
#define ASTRIDE 36

__global__ __launch_bounds__(256, 2) void gemm_mma_kernel(
    const float* __restrict__ x, const float* __restrict__ W, int n)
{
    __shared__ float As[128][ASTRIDE];
    __shared__ float Bs[128][ASTRIDE];

    const int tid  = threadIdx.x;
    const int wid  = tid >> 5;
    const int lane = tid & 31;
    const int gq   = lane >> 2;
    const int tq   = lane & 3;
    const int warpM = wid & 3;
    const int warpN = wid >> 2;
    const int rowBase = blockIdx.x * 128;

    float acc[2][8][4];
    #pragma unroll
    for (int mt = 0; mt < 2; mt++)
        #pragma unroll
        for (int nt = 0; nt < 8; nt++)
            #pragma unroll
            for (int q = 0; q < 4; q++) acc[mt][nt][q] = 0.0f;

    #pragma unroll
    for (int chunk = 0; chunk < 4; chunk++) {
        #pragma unroll
        for (int it = 0; it < 4; it++) {
            int gid = tid + it * 256;
            int row = gid >> 3;
            int f4  = gid & 7;
            int gm = rowBase + row;
            float4 av = make_float4(0.f, 0.f, 0.f, 0.f);
            if (gm < n) av = *reinterpret_cast<const float4*>(&x[(size_t)gm * NIN + chunk * KC + f4 * 4]);
            *reinterpret_cast<float4*>(&As[row][f4 * 4]) = av;
            float4 bv = *reinterpret_cast<const float4*>(&W[(size_t)row * NIN + chunk * KC + f4 * 4]);
            *reinterpret_cast<float4*>(&Bs[row][f4 * 4]) = bv;
        }
        __syncthreads();

        #pragma unroll
        for (int ks = 0; ks < 4; ks++) {
            uint32_t ahi[2][4], alo[2][4];
            #pragma unroll
            for (int mt = 0; mt < 2; mt++) {
                int r0 = warpM * 32 + mt * 16 + gq;
                int c0 = ks * 8 + tq;
                float v0 = As[r0][c0];
                float v1 = As[r0 + 8][c0];
                float v2 = As[r0][c0 + 4];
                float v3 = As[r0 + 8][c0 + 4];
                float h0 = to_tf32(v0), h1 = to_tf32(v1), h2 = to_tf32(v2), h3 = to_tf32(v3);
                ahi[mt][0] = __float_as_uint(h0);
                ahi[mt][1] = __float_as_uint(h1);
                ahi[mt][2] = __float_as_uint(h2);
                ahi[mt][3] = __float_as_uint(h3);
                alo[mt][0] = __float_as_uint(to_tf32(v0 - h0));
                alo[mt][1] = __float_as_uint(to_tf32(v1 - h1));
                alo[mt][2] = __float_as_uint(to_tf32(v2 - h2));
                alo[mt][3] = __float_as_uint(to_tf32(v3 - h3));
            }
            #pragma unroll
            for (int nt = 0; nt < 8; nt++) {
                int nrow = warpN * 64 + nt * 8 + gq;
                float w0 = Bs[nrow][ks * 8 + tq];
                float w1 = Bs[nrow][ks * 8 + tq + 4];
                float h0 = to_tf32(w0), h1 = to_tf32(w1);
                uint32_t bh0 = __float_as_uint(h0), bh1 = __float_as_uint(h1);
                uint32_t bl0 = __float_as_uint(to_tf32(w0 - h0));
                uint32_t bl1 = __float_as_uint(to_tf32(w1 - h1));
                #pragma unroll
                for (int mt = 0; mt < 2; mt++) {
                    mma8(acc[mt][nt], ahi[mt], bh0, bh1);
                    mma8(acc[mt][nt], ahi[mt], bl0, bl1);
                    mma8(acc[mt][nt], alo[mt], bh0, bh1);
                }
            }
        }
        __syncthreads();
    }

    // ---- epilogue: convert to half2, write g_h (unscaled) ----
    #pragma unroll
    for (int mt = 0; mt < 2; mt++) {
        int r0 = rowBase + warpM * 32 + mt * 16 + gq;
        int r1 = r0 + 8;
        #pragma unroll
        for (int nt = 0; nt < 8; nt++) {
            int c = warpN * 64 + nt * 8 + 2 * tq;
            if (r0 < n)
                g_h[(size_t)r0 * 64 + (c >> 1)] =
                    __floats2half2_rn(acc[mt][nt][0], acc[mt][nt][1]);
            if (r1 < n)
                g_h[(size_t)r1 * 64 + (c >> 1)] =
                    __floats2half2_rn(acc[mt][nt][2], acc[mt][nt][3]);
        }
    }
}

// ---------------- Pull aggregation: one warp per destination node -------------
// out[i] = dinv[i] * ( dinv[i]*h[i] + sum_e dinv[src_e]*h[src_e] ) + b
__global__ __launch_bounds__(256) void aggregate_kernel(
    float* __restrict__ out, const float* __restrict__ b, int n)
{
    const uint2* gh2 = reinterpret_cast<const uint2*>(g_h);
    int w    = (blockIdx.x * blockDim.x + threadIdx.x) >> 5;
    int lane = threadIdx.x & 31;
    if (w >= n) return;

    float sdi = g_dinv[w];
    float4 acc;
    {   // self-loop term: dinv[w] * h[w]
        uint2 v = gh2[(size_t)w * 32 + lane];
        float2 f0 = __half22float2(*reinterpret_cast<__half2*>(&v.x));
        float2 f1 = __half22float2(*reinterpret_cast<__half2*>(&v.y));
        acc = make_float4(sdi * f0.x, sdi * f0.y, sdi * f1.x, sdi * f1.y);
    }
    int beg = g_indptr[w];
    int num = g_cnt[w];

    int e = 0;
    for (; e + 7 < num; e += 8) {
        int   s[8];
        uint2 v[8];
        float d[8];
        #pragma unroll
        for (int q = 0; q < 8; q++) s[q] = g_eidx[beg + e + q];
        #pragma unroll
        for (int q = 0; q < 8; q++) { v[q] = gh2[(size_t)s[q] * 32 + lane]; d[q] = g_dinv[s[q]]; }
        #pragma unroll
        for (int q = 0; q < 8; q++) {
            float2 f0 = __half22float2(*reinterpret_cast<__half2*>(&v[q].x));
            float2 f1 = __half22float2(*reinterpret_cast<__half2*>(&v[q].y));
            acc.x = fmaf(d[q], f0.x, acc.x);
            acc.y = fmaf(d[q], f0.y, acc.y);
            acc.z = fmaf(d[q], f1.x, acc.z);
            acc.w = fmaf(d[q], f1.y, acc.w);
        }
    }
    for (; e < num; e++) {
        int s0 = g_eidx[beg + e];
        uint2 v = gh2[(size_t)s0 * 32 + lane];
        float dq = g_dinv[s0];
        float2 f0 = __half22float2(*reinterpret_cast<__half2*>(&v.x));
        float2 f1 = __half22float2(*reinterpret_cast<__half2*>(&v.y));
        acc.x = fmaf(dq, f0.x, acc.x);
        acc.y = fmaf(dq, f0.y, acc.y);
        acc.z = fmaf(dq, f1.x, acc.z);
        acc.w = fmaf(dq, f1.y, acc.w);
    }

    const float4* b4 = reinterpret_cast<const float4*>(b);
    float4 bb = b4[lane];
    float4 o;
    o.x = fmaf(acc.x, sdi, bb.x);
    o.y = fmaf(acc.y, sdi, bb.y);
    o.z = fmaf(acc.z, sdi, bb.z);
    o.w = fmaf(acc.w, sdi, bb.w);
    reinterpret_cast<float4*>(out)[(size_t)w * 32 + lane] = o;
}

// ---------------- launch: fork GEMM onto a side stream ------------------------

extern "C" void kernel_launch(void* const* d_in, const int* in_sizes, int n_in,
                              void* d_out, int out_size) {
    const float* x  = (const float*)d_in[0];
    const int*   ei = (const int*)d_in[1];     // int32 (JAX x64 disabled)
    const float* W  = (const float*)d_in[3];
    const float* b  = (const float*)d_in[4];
    float*       out = (float*)d_out;

    int n = in_sizes[0] / NIN;
    int E = in_sizes[1] / 2;
    int nb = (n + SCAN_B - 1) / SCAN_B;

    // Per-call stream/events (call count is tiny: correctness + capture).
    cudaStream_t s2;
    cudaEvent_t evF, evJ;
    cudaStreamCreateWithFlags(&s2, cudaStreamNonBlocking);
    cudaEventCreateWithFlags(&evF, cudaEventDisableTiming);
    cudaEventCreateWithFlags(&evJ, cudaEventDisableTiming);

    // Fork: GEMM (depends only on x, W) runs concurrently with CSR build.
    cudaEventRecord(evF, 0);
    cudaStreamWaitEvent(s2, evF, 0);
    gemm_mma_kernel<<<(n + 127) / 128, 256, 0, s2>>>(x, W, n);
    cudaEventRecord(evJ, s2);

    // CSR build chain on the main (captured) stream.
    void* cnt_ptr = nullptr;
    cudaGetSymbolAddress(&cnt_ptr, g_cnt);
    cudaMemsetAsync(cnt_ptr, 0, (size_t)n * sizeof(int));
    int qE = (E + 3) / 4;
    cnt_count_kernel<<<(qE + 255) / 256, 256>>>(ei, E, n);
    scan_block_kernel<<<nb, SCAN_B>>>(n);
    addback_kernel<<<(n + 255) / 256, 256>>>(n);
    fill_kernel<<<(qE + 255) / 256, 256>>>(ei, E, n);

    // Join, then aggregate.
    cudaStreamWaitEvent(0, evJ, 0);
    long long agg_threads = (long long)n * 32;
    aggregate_kernel<<<(int)((agg_threads + 255) / 256), 256>>>(out, b, n);
}